// round 1
// baseline (speedup 1.0000x reference)
#include <cuda_runtime.h>
#include <cuda_bf16.h>

#define NSIDE 256
#define LAM   0.05f   // STEP = ALPHA/2
#define TOLV  0.01f
#define NITER 35

// Persistent DR state (device globals; no allocation allowed).
// pT: p stored transposed (only the column phase uses p -> contiguous access).
// xT: transposed mirror of x (d_out) so the column phase reads contiguously.
__device__ float g_pT[NSIDE * NSIDE];
__device__ float g_q [NSIDE * NSIDE];
__device__ float g_y [NSIDE * NSIDE];
__device__ float g_xT[NSIDE * NSIDE];
__device__ float g_acc;       // residual from previous iteration (inf initially)
__device__ int   g_acc2bits;  // accumulator for this iteration's max|y - x2| (nonneg float bits)

// Exact 1D TV prox: Condat's direct algorithm (same unique minimizer as the
// reference's taut-string construction). Runs on one thread over shared memory.
__device__ __forceinline__ void tv1d_condat(const float* __restrict__ y,
                                            float* __restrict__ x, float lam)
{
    const int width = NSIDE;
    int k = 0, k0 = 0, kplus = 0, kminus = 0;
    const float twolambda = 2.0f * lam;
    const float minlambda = -lam;
    float umin = lam, umax = minlambda;
    float vmin = y[0] - lam, vmax = y[0] + lam;
    for (;;) {
        while (k == width - 1) {
            if (umin < 0.0f) {
                do { x[k0++] = vmin; } while (k0 <= kminus);
                k = k0; kminus = k0;
                vmin = y[k];
                umin = lam;
                umax = vmin + lam - vmax;
            } else if (umax > 0.0f) {
                do { x[k0++] = vmax; } while (k0 <= kplus);
                k = k0; kplus = k0;
                vmax = y[k];
                umax = minlambda;
                umin = vmax - lam - vmin;
            } else {
                vmin += umin / (float)(k - k0 + 1);
                do { x[k0++] = vmin; } while (k0 <= k);
                return;
            }
        }
        float yk1 = y[k + 1];
        if (yk1 + umin < vmin - lam) {           // negative jump
            do { x[k0++] = vmin; } while (k0 <= kminus);
            k = k0; kminus = k0; kplus = k0;
            vmin = y[k];
            vmax = vmin + twolambda;
            umin = lam; umax = minlambda;
        } else if (yk1 + umax > vmax + lam) {    // positive jump
            do { x[k0++] = vmax; } while (k0 <= kplus);
            k = k0; kminus = k0; kplus = k0;
            vmax = y[k];
            vmin = vmax - twolambda;
            umin = lam; umax = minlambda;
        } else {                                  // no jump
            k++;
            umin += y[k] - vmin;
            umax += y[k] - vmax;
            if (umin >= lam) {
                vmin += (umin - lam) / (float)(k - k0 + 1);
                umin = lam;
                kminus = k;
            }
            if (umax <= minlambda) {
                vmax += (umax + lam) / (float)(k - k0 + 1);
                umax = minlambda;
                kplus = k;
            }
        }
    }
}

__global__ void k_init(const float* __restrict__ X, float* __restrict__ x)
{
    int i = blockIdx.x * blockDim.x + threadIdx.x;
    float v = X[i];
    x[i] = v;
    int r = i >> 8, c = i & (NSIDE - 1);
    g_xT[c * NSIDE + r] = v;   // one-time strided transpose write
    g_pT[i] = 0.0f;
    g_q[i]  = 0.0f;
    if (i == 0) g_acc = __int_as_float(0x7f800000);  // +inf
}

// Column phase: y = prox_tv1d(x + p) per column; p <- (x + p) - y.
// One warp per column j; reads xT/pT rows contiguously.
__global__ void k_cols()
{
    if (g_acc < TOLV) return;   // while_loop condition: acc >= tol
    __shared__ float s[NSIDE], o[NSIDE];
    int j = blockIdx.x;
    int lane = threadIdx.x;
    if (j == 0 && lane == 0) g_acc2bits = 0;

    const float* __restrict__ xT = g_xT + j * NSIDE;
    float* __restrict__ pT = g_pT + j * NSIDE;

#pragma unroll
    for (int t = 0; t < NSIDE / 32; t++) {
        int i = lane + t * 32;
        s[i] = xT[i] + pT[i];
    }
    __syncwarp();
    if (lane == 0) tv1d_condat(s, o, LAM);
    __syncwarp();
#pragma unroll
    for (int t = 0; t < NSIDE / 32; t++) {
        int i = lane + t * 32;
        float ov = o[i];
        g_y[i * NSIDE + j] = ov;   // strided write (unavoidable orientation flip)
        pT[i] = s[i] - ov;
    }
}

// Row phase: x2 = prox_tv1d(y + q) per row; q <- (y + q) - x2; acc = max|y - x2|.
__global__ void k_rows(float* __restrict__ x)
{
    if (g_acc < TOLV) return;
    __shared__ float s[NSIDE], o[NSIDE];
    int r = blockIdx.x;
    int lane = threadIdx.x;

    const float* __restrict__ yrow = g_y + r * NSIDE;
    float* __restrict__ qrow = g_q + r * NSIDE;

#pragma unroll
    for (int t = 0; t < NSIDE / 32; t++) {
        int i = lane + t * 32;
        s[i] = yrow[i] + qrow[i];
    }
    __syncwarp();
    if (lane == 0) tv1d_condat(s, o, LAM);
    __syncwarp();

    float m = 0.0f;
#pragma unroll
    for (int t = 0; t < NSIDE / 32; t++) {
        int i = lane + t * 32;
        float ov = o[i];
        float sv = s[i];
        float qold = qrow[i];
        x[r * NSIDE + i] = ov;       // d_out, coalesced
        g_xT[i * NSIDE + r] = ov;    // strided mirror for next column phase
        qrow[i] = sv - ov;
        m = fmaxf(m, fabsf((sv - qold) - ov));   // |y - x2|
    }
#pragma unroll
    for (int off = 16; off; off >>= 1)
        m = fmaxf(m, __shfl_xor_sync(0xffffffffu, m, off));
    if (lane == 0) atomicMax(&g_acc2bits, __float_as_int(m));  // nonneg floats: int order OK
}

__global__ void k_commit()
{
    if (g_acc >= TOLV) g_acc = __int_as_float(g_acc2bits);
}

extern "C" void kernel_launch(void* const* d_in, const int* in_sizes, int n_in,
                              void* d_out, int out_size)
{
    const float* X = (const float*)d_in[0];
    float* x = (float*)d_out;

    k_init<<<(NSIDE * NSIDE) / 256, 256>>>(X, x);
    for (int t = 0; t < NITER; t++) {
        k_cols<<<NSIDE, 32>>>();
        k_rows<<<NSIDE, 32>>>(x);
        k_commit<<<1, 1>>>();
    }
}

// round 2
// speedup vs baseline: 1.3465x; 1.3465x over previous
#include <cuda_runtime.h>
#include <cuda_bf16.h>

#define NSIDE 256
#define NB    256
#define LAM   0.05f   // STEP = ALPHA/2
#define TOLV  0.01f
#define NITER 35

// Cross-block exchange buffers (only y and x-transposed need to cross blocks;
// p and q are block-private and live in shared memory).
__device__ float g_y [NSIDE * NSIDE];
__device__ float g_xT[NSIDE * NSIDE];

// Grid barrier + residual state. Zero-initialized at module load; self-resetting
// across graph replays (count returns to 0, epoch grows monotonically).
__device__ unsigned          g_cnt;
__device__ volatile unsigned g_ep;
__device__ volatile int      g_stop;
__device__ int               g_accbits;

// Exact 1D TV prox (Condat 2013) with register prefetch of y[k+1]/y[k+2]
// to pull the SMEM load off the dependent chain. y must be padded to >= n+2.
__device__ __forceinline__ void tv1d_condat(const float* __restrict__ y,
                                            float* __restrict__ x)
{
    const int width = NSIDE;
    const float lam = LAM, twolam = 2.0f * LAM, mlam = -LAM;
    int k = 0, k0 = 0, kplus = 0, kminus = 0;
    float umin = lam, umax = mlam;
    float vmin = y[0] - lam, vmax = y[0] + lam;
    float ynext = y[1];
    for (;;) {
        while (k == width - 1) {
            if (umin < 0.0f) {
                do { x[k0++] = vmin; } while (k0 <= kminus);
                k = k0; kminus = k0;
                vmin = y[k];
                umin = lam;
                umax = vmin + lam - vmax;
            } else if (umax > 0.0f) {
                do { x[k0++] = vmax; } while (k0 <= kplus);
                k = k0; kplus = k0;
                vmax = y[k];
                umax = mlam;
                umin = vmax - lam - vmin;
            } else {
                vmin += umin / (float)(k - k0 + 1);
                do { x[k0++] = vmin; } while (k0 <= k);
                return;
            }
            ynext = y[k + 1];      // padded read; unused if k==width-1 again
        }
        float yspec = y[k + 2];    // speculative prefetch (padded)
        if (ynext + umin < vmin - lam) {           // negative jump
            do { x[k0++] = vmin; } while (k0 <= kminus);
            k = k0; kminus = k0; kplus = k0;
            vmin = y[k];
            vmax = vmin + twolam;
            umin = lam; umax = mlam;
            ynext = y[k + 1];
        } else if (ynext + umax > vmax + lam) {    // positive jump
            do { x[k0++] = vmax; } while (k0 <= kplus);
            k = k0; kminus = k0; kplus = k0;
            vmax = y[k];
            vmin = vmax - twolam;
            umin = lam; umax = mlam;
            ynext = y[k + 1];
        } else {                                    // no jump (common path)
            k++;
            umin += ynext - vmin;
            umax += ynext - vmax;
            if (umin >= lam)  { vmin += (umin - lam) / (float)(k - k0 + 1); umin = lam;  kminus = k; }
            if (umax <= mlam) { vmax += (umax + lam) / (float)(k - k0 + 1); umax = mlam; kplus  = k; }
            ynext = yspec;
        }
    }
}

// Grid barrier: sense via monotonically increasing epoch. Only lane 0 arrives/
// spins; all lanes fence after release. If doCommit, the last-arriving block
// converts the accumulated residual to the stop decision and resets it.
__device__ __forceinline__ void gridbar(unsigned& ep, bool doCommit)
{
    __syncwarp();
    ep += 1;
    if (threadIdx.x == 0) {
        __threadfence();
        unsigned old = atomicAdd(&g_cnt, 1u);
        if (old == NB - 1) {
            __threadfence();
            if (doCommit) {
                g_stop = (__int_as_float(g_accbits) < TOLV) ? 1 : 0;
                g_accbits = 0;
            }
            atomicExch(&g_cnt, 0u);
            __threadfence();
            g_ep = ep;
        } else {
            while ((int)(g_ep - ep) < 0) { }
        }
    }
    __syncwarp();
    __threadfence();
}

__global__ void __launch_bounds__(32)
tv2d_persistent(const float* __restrict__ X, float* __restrict__ x)
{
    __shared__ float s[NSIDE + 2], o[NSIDE], p[NSIDE], q[NSIDE];
    const int b = blockIdx.x;
    const int lane = threadIdx.x;
    unsigned ep = g_ep;   // no barrier in flight at launch -> consistent

#pragma unroll
    for (int t = 0; t < NSIDE / 32; t++) {
        int i = lane + t * 32;
        p[i] = 0.0f;
        q[i] = 0.0f;
    }
    if (lane == 0) { s[NSIDE] = 0.0f; s[NSIDE + 1] = 0.0f; }

    for (int it = 0; it < NITER; it++) {
        // ---- column phase: this block owns column b ----
#pragma unroll
        for (int t = 0; t < NSIDE / 32; t++) {
            int i = lane + t * 32;
            float xv = (it == 0) ? X[i * NSIDE + b] : g_xT[b * NSIDE + i];
            s[i] = xv + p[i];
        }
        __syncwarp();
        if (lane == 0) tv1d_condat(s, o);
        __syncwarp();
#pragma unroll
        for (int t = 0; t < NSIDE / 32; t++) {
            int i = lane + t * 32;
            float ov = o[i];
            p[i] = s[i] - ov;
            g_y[i * NSIDE + b] = ov;      // strided column write
        }
        gridbar(ep, false);

        // ---- row phase: this block owns row b ----
#pragma unroll
        for (int t = 0; t < NSIDE / 32; t++) {
            int i = lane + t * 32;
            s[i] = g_y[b * NSIDE + i] + q[i];
        }
        __syncwarp();
        if (lane == 0) tv1d_condat(s, o);
        __syncwarp();

        float m = 0.0f;
#pragma unroll
        for (int t = 0; t < NSIDE / 32; t++) {
            int i = lane + t * 32;
            float ov = o[i];
            float sv = s[i];
            float qo = q[i];
            q[i] = sv - ov;
            x[b * NSIDE + i] = ov;         // d_out (coalesced)
            g_xT[i * NSIDE + b] = ov;      // transposed mirror for next cols
            m = fmaxf(m, fabsf((sv - qo) - ov));   // |y - x2|
        }
#pragma unroll
        for (int off = 16; off; off >>= 1)
            m = fmaxf(m, __shfl_xor_sync(0xffffffffu, m, off));
        if (lane == 0) atomicMax(&g_accbits, __float_as_int(m));

        gridbar(ep, true);
        if (g_stop) break;    // DR converged: skip remaining iterations entirely
    }
}

extern "C" void kernel_launch(void* const* d_in, const int* in_sizes, int n_in,
                              void* d_out, int out_size)
{
    const float* X = (const float*)d_in[0];
    float* x = (float*)d_out;
    tv2d_persistent<<<NB, 32>>>(X, x);
}